// round 10
// baseline (speedup 1.0000x reference)
#include <cuda_runtime.h>
#include <cstdint>

// Problem constants (fixed-shape variant)
#define BS 4
#define NQ 10000
#define NH 8
#define HD 32
#define NP 4
#define SH 100
#define SW 100

// value layout: [b][pix][h][d], pix = y*SW + x  (pixel stride = 256 floats = 1024 B)
// loc: [b][q][h][0][p][2]   aw: [b][q][h][0][p]   out: [b][q][h*HD+d]
//
// One warp = (b, q, h). lane = channel d (0..31). Every corner gather is
// 32 lanes x 4B = exactly one 128B line => one L1 wavefront at the fast
// cross-LDG rate (no within-LDG replays).
//
// Scalar bilinear math: lane c = lane&3 computes point c's package once,
// packs {w00,w10,w01,w11} (float4) and {o00,o10,o01,o11} (int4, byte
// offsets) into smem; consume loop reads them via uniform-broadcast LDS.128.

__global__ __launch_bounds__(256) void deform_attn_kernel_v4(
    const float* __restrict__ value,
    const float* __restrict__ loc,
    const float* __restrict__ aw,
    float* __restrict__ out)
{
    __shared__ float4 s_w[8][NP];   // [warp-in-block][point]
    __shared__ int4   s_o[8][NP];

    const int tid  = threadIdx.x;
    const int wib  = tid >> 5;                       // warp in block (0..7)
    const int lane = tid & 31;
    const int w    = blockIdx.x * 8 + wib;           // global warp = (b*NQ+q)*NH + h
    if (w >= BS * NQ * NH) return;

    const int h  = w & (NH - 1);
    const int bq = w >> 3;                           // b*NQ + q
    const int b  = bq / NQ;

    // ---------- compute phase (lane c = lane&3; lanes 0..3 publish) ----------
    {
        const int c   = lane & 3;
        const int idx = w * NP + c;

        const float2 l  = __ldg(reinterpret_cast<const float2*>(loc) + idx);
        const float  wg = __ldg(aw + idx);

        const float x = fmaf(l.x, (float)SW, -0.5f);
        const float y = fmaf(l.y, (float)SH, -0.5f);
        const int x0 = __float2int_rd(x);
        const int y0 = __float2int_rd(y);
        const float tx = x - (float)x0;
        const float ty = y - (float)y0;

        // factored weights: 6 mul/fma
        const float wy1 = ty * wg;
        const float wy0 = wg - wy1;
        float w00 = fmaf(-tx, wy0, wy0);
        float w10 = tx * wy0;
        float w01 = fmaf(-tx, wy1, wy1);
        float w11 = tx * wy1;

        const bool vx0 = (unsigned)x0       < (unsigned)SW;
        const bool vx1 = (unsigned)(x0 + 1) < (unsigned)SW;
        const bool vy0 = (unsigned)y0       < (unsigned)SH;
        const bool vy1 = (unsigned)(y0 + 1) < (unsigned)SH;

        if (!vx0) { w00 = 0.f; w01 = 0.f; }
        if (!vx1) { w10 = 0.f; w11 = 0.f; }
        if (!vy0) { w00 = 0.f; w10 = 0.f; }
        if (!vy1) { w01 = 0.f; w11 = 0.f; }

        const int xs0 = vx0 ? x0 : 0;
        const int xs1 = vx1 ? (x0 + 1) : 0;
        const int ys0 = vy0 ? y0 : 0;
        const int ys1 = vy1 ? (y0 + 1) : 0;

        // byte offsets within this batch's image: pix * 1024
        const int ra = ys0 * (SW * 1024);
        const int rb = ys1 * (SW * 1024);
        const int ca = xs0 << 10;
        const int cb = xs1 << 10;

        if (lane < NP) {
            s_w[wib][lane] = make_float4(w00, w10, w01, w11);
            s_o[wib][lane] = make_int4(ra + ca, ra + cb, rb + ca, rb + cb);
        }
    }
    __syncwarp();

    // ---------- consume phase ----------
    // base: value + (b*H*W*NH*HD + h*HD + lane) floats
    const char* __restrict__ base =
        reinterpret_cast<const char*>(value) +
        ((size_t)b * (SH * SW * NH * HD) + h * HD + lane) * sizeof(float);

    float accA = 0.f, accB = 0.f;

#pragma unroll
    for (int p = 0; p < NP; ++p) {
        const float4 W = s_w[wib][p];
        const int4   O = s_o[wib][p];

        const float v00 = __ldg(reinterpret_cast<const float*>(base + O.x));
        const float v10 = __ldg(reinterpret_cast<const float*>(base + O.y));
        const float v01 = __ldg(reinterpret_cast<const float*>(base + O.z));
        const float v11 = __ldg(reinterpret_cast<const float*>(base + O.w));

        accA = fmaf(W.x, v00, accA);
        accB = fmaf(W.y, v10, accB);
        accA = fmaf(W.z, v01, accA);
        accB = fmaf(W.w, v11, accB);
    }

    // out: [b][q][h*HD + d] -> float index w*32 + lane (contiguous, 1 line/warp)
    out[(size_t)w * HD + lane] = accA + accB;
}

extern "C" void kernel_launch(void* const* d_in, const int* in_sizes, int n_in,
                              void* d_out, int out_size)
{
    const float* value = (const float*)d_in[0];
    // d_in[1] = value_spatial_shapes (int64), unused
    const float* loc = (const float*)d_in[2];
    const float* aw = (const float*)d_in[3];
    float* out = (float*)d_out;

    const int total_warps = BS * NQ * NH;            // 320000
    const int threads = 256;                          // 8 warps per block
    const int blocks = total_warps / 8;               // 40000

    deform_attn_kernel_v4<<<blocks, threads>>>(value, loc, aw, out);
}

// round 11
// speedup vs baseline: 1.1927x; 1.1927x over previous
#include <cuda_runtime.h>
#include <cstdint>

// Problem constants (fixed-shape variant)
#define BS 4
#define NQ 10000
#define NH 8
#define HD 32
#define NP 4
#define SH 100
#define SW 100

// value layout: [b][pix][h][d], pix = y*SW + x
//   byte offset for (pix, h, d): pix*1024 + h*128 + d*4
// loc: [b][q][h][0][p][2]   aw: [b][q][h][0][p]   out: [b][q][h*HD+d]
//
// One warp = one (b, q): covers all 8 heads x 4 points = 32 combos.
//   Compute phase: lane = combo (head = lane>>2, point = lane&3) -> every
//   lane computes a UNIQUE bilinear package (4 masked weights, 4 byte
//   offsets incl. head term) and publishes it to smem. Zero redundancy.
//   Consume phase: lane = channel. Each corner gather = 32 lanes x 4B =
//   exactly one 128B line (fast cross-LDG L1 wavefront rate, no replays).

__global__ __launch_bounds__(256) void deform_attn_kernel_v5(
    const float* __restrict__ value,
    const float* __restrict__ loc,
    const float* __restrict__ aw,
    float* __restrict__ out)
{
    __shared__ float4 s_w[8][32];   // [warp-in-block][combo]
    __shared__ int4   s_o[8][32];

    const int tid  = threadIdx.x;
    const int wib  = tid >> 5;
    const int lane = tid & 31;
    const int bq   = blockIdx.x * 8 + wib;          // b*NQ + q  (exact: 40000 warps)
    const int b    = bq / NQ;

    // ---------- compute phase: one unique combo per lane ----------
    {
        const int idx = bq * 32 + lane;             // ((b*NQ+q)*NH + head)*NP + point

        const float2 l  = __ldg(reinterpret_cast<const float2*>(loc) + idx);
        const float  wg = __ldg(aw + idx);

        const float x = fmaf(l.x, (float)SW, -0.5f);
        const float y = fmaf(l.y, (float)SH, -0.5f);
        const int x0 = __float2int_rd(x);
        const int y0 = __float2int_rd(y);
        const float tx = x - (float)x0;
        const float ty = y - (float)y0;

        // factored weights: 6 mul/fma
        const float wy1 = ty * wg;
        const float wy0 = wg - wy1;
        float w00 = fmaf(-tx, wy0, wy0);
        float w10 = tx * wy0;
        float w01 = fmaf(-tx, wy1, wy1);
        float w11 = tx * wy1;

        const bool vx0 = (unsigned)x0       < (unsigned)SW;
        const bool vx1 = (unsigned)(x0 + 1) < (unsigned)SW;
        const bool vy0 = (unsigned)y0       < (unsigned)SH;
        const bool vy1 = (unsigned)(y0 + 1) < (unsigned)SH;

        if (!vx0) { w00 = 0.f; w01 = 0.f; }
        if (!vx1) { w10 = 0.f; w11 = 0.f; }
        if (!vy0) { w00 = 0.f; w10 = 0.f; }
        if (!vy1) { w01 = 0.f; w11 = 0.f; }

        const int xs0 = vx0 ? x0 : 0;
        const int xs1 = vx1 ? (x0 + 1) : 0;
        const int ys0 = vy0 ? y0 : 0;
        const int ys1 = vy1 ? (y0 + 1) : 0;

        // byte offsets: pix*1024 + head*128
        const int hterm = (lane >> 2) << 7;
        const int ra = ys0 * (SW * 1024) + hterm;
        const int rb = ys1 * (SW * 1024) + hterm;
        const int ca = xs0 << 10;
        const int cb = xs1 << 10;

        s_w[wib][lane] = make_float4(w00, w10, w01, w11);
        s_o[wib][lane] = make_int4(ra + ca, ra + cb, rb + ca, rb + cb);
    }
    __syncwarp();

    // ---------- consume phase: lane = channel ----------
    const char* __restrict__ base =
        reinterpret_cast<const char*>(value) +
        ((size_t)b * (SH * SW * NH * HD) + lane) * sizeof(float);

    float acc[NH];
#pragma unroll
    for (int h = 0; h < NH; ++h) acc[h] = 0.f;

#pragma unroll
    for (int h = 0; h < NH; ++h) {
#pragma unroll
        for (int p = 0; p < NP; ++p) {
            const int s = h * NP + p;
            const float4 W = s_w[wib][s];
            const int4   O = s_o[wib][s];

            const float v00 = __ldg(reinterpret_cast<const float*>(base + O.x));
            const float v10 = __ldg(reinterpret_cast<const float*>(base + O.y));
            const float v01 = __ldg(reinterpret_cast<const float*>(base + O.z));
            const float v11 = __ldg(reinterpret_cast<const float*>(base + O.w));

            acc[h] = fmaf(W.x, v00, acc[h]);
            acc[h] = fmaf(W.y, v10, acc[h]);
            acc[h] = fmaf(W.z, v01, acc[h]);
            acc[h] = fmaf(W.w, v11, acc[h]);
        }
    }

    // out: [b][q][h*32 + lane] -> 8 coalesced 128B stores
    float* __restrict__ op = out + (size_t)bq * (NH * HD) + lane;
#pragma unroll
    for (int h = 0; h < NH; ++h) op[h * HD] = acc[h];
}

extern "C" void kernel_launch(void* const* d_in, const int* in_sizes, int n_in,
                              void* d_out, int out_size)
{
    const float* value = (const float*)d_in[0];
    // d_in[1] = value_spatial_shapes (int64), unused
    const float* loc = (const float*)d_in[2];
    const float* aw = (const float*)d_in[3];
    float* out = (float*)d_out;

    const int total_warps = BS * NQ;                 // 40000 (one per (b,q))
    const int threads = 256;                          // 8 warps per block
    const int blocks = total_warps / 8;               // 5000

    deform_attn_kernel_v5<<<blocks, threads>>>(value, loc, aw, out);
}

// round 12
// speedup vs baseline: 1.5465x; 1.2967x over previous
#include <cuda_runtime.h>
#include <cstdint>

// Problem constants (fixed-shape variant)
#define BS 4
#define NQ 10000
#define NH 8
#define HD 32
#define NP 4
#define SH 100
#define SW 100

// value layout: [b][pix][h][d], pix = y*SW + x  (pixel stride = 256 floats = 64 float4)
// loc: [b][q][h][0][p][2]   aw: [b][q][h][0][p]   out: [b][q][h*HD+d]
//
// One warp = (b, q, head-group hg) covering heads hg*4..hg*4+3.
// Consume mapping: g = lane>>3 (head in group), sub = lane&7 (float4 slot).
// Scalar bilinear math for the 16 (head,point) combos computed once by
// lanes 0..15 and broadcast via shfl.
// __launch_bounds__(256, 6) forces regs<=40 -> 6 CTAs/SM (48 warps).

__global__ __launch_bounds__(256, 6) void deform_attn_kernel_v6(
    const float* __restrict__ value,
    const float* __restrict__ loc,
    const float* __restrict__ aw,
    float* __restrict__ out)
{
    const int gtid = blockIdx.x * blockDim.x + threadIdx.x;
    const int warp = gtid >> 5;
    const int lane = gtid & 31;

    const int hg = warp & 1;
    const int bq = warp >> 1;           // b*NQ + q
    const int b  = bq / NQ;

    // ---- compute phase: lane c = lane&15 computes one (head, point) combo
    const int c   = lane & 15;          // head gc = c>>2, point pc = c&3
    const int idx = bq * (NH * NP) + (hg << 4) + c;

    const float2 l = __ldg(reinterpret_cast<const float2*>(loc) + idx);
    const float  w = __ldg(aw + idx);

    const float x = fmaf(l.x, (float)SW, -0.5f);
    const float y = fmaf(l.y, (float)SH, -0.5f);
    const int x0 = __float2int_rd(x);
    const int y0 = __float2int_rd(y);
    const float tx = x - (float)x0;
    const float ty = y - (float)y0;

    // factored weights: 6 mul/fma
    float wy1 = ty * w;
    float wy0 = w - wy1;
    float w00 = fmaf(-tx, wy0, wy0);
    float w10 = tx * wy0;
    float w01 = fmaf(-tx, wy1, wy1);
    float w11 = tx * wy1;

    const bool vx0 = (unsigned)x0       < (unsigned)SW;
    const bool vx1 = (unsigned)(x0 + 1) < (unsigned)SW;
    const bool vy0 = (unsigned)y0       < (unsigned)SH;
    const bool vy1 = (unsigned)(y0 + 1) < (unsigned)SH;

    if (!vx0) { w00 = 0.f; w01 = 0.f; }
    if (!vx1) { w10 = 0.f; w11 = 0.f; }
    if (!vy0) { w00 = 0.f; w10 = 0.f; }
    if (!vy1) { w01 = 0.f; w11 = 0.f; }

    const int xs0 = vx0 ? x0 : 0;
    const int xs1 = vx1 ? (x0 + 1) : 0;
    const int ys0 = vy0 ? y0 : 0;
    const int ys1 = vy1 ? (y0 + 1) : 0;

    // float4-unit offsets: pix*64 + head*8 (head = hg*4 + gc)
    const int hterm = ((hg << 2) + (c >> 2)) << 3;
    const int ra  = ys0 * (SW * 64) + hterm;
    const int dRb = (ys1 - ys0) * (SW * 64);     // rb = ra + dRb
    const int o00 = ra + (xs0 << 6);
    const int o10 = ra + (xs1 << 6);

    // ---- consume phase
    const int sub = lane & 7;
    const float4* __restrict__ vb =
        reinterpret_cast<const float4*>(value) +
        (size_t)b * (SH * SW * (NH * HD / 4)) + sub;

    const int srcbase = (lane >> 3) << 2;   // combos for my head: srcbase + p

    float4 accA = make_float4(0.f, 0.f, 0.f, 0.f);
    float4 accB = make_float4(0.f, 0.f, 0.f, 0.f);

#pragma unroll
    for (int p = 0; p < NP; ++p) {
        const int s = srcbase + p;
        const float W00 = __shfl_sync(0xffffffffu, w00, s);
        const float W10 = __shfl_sync(0xffffffffu, w10, s);
        const float W01 = __shfl_sync(0xffffffffu, w01, s);
        const float W11 = __shfl_sync(0xffffffffu, w11, s);
        const int   O00 = __shfl_sync(0xffffffffu, o00, s);
        const int   O10 = __shfl_sync(0xffffffffu, o10, s);
        const int   DRB = __shfl_sync(0xffffffffu, dRb, s);

        const float4 v00 = __ldg(vb + O00);
        const float4 v10 = __ldg(vb + O10);
        const float4 v01 = __ldg(vb + O00 + DRB);
        const float4 v11 = __ldg(vb + O10 + DRB);

        accA.x = fmaf(W00, v00.x, accA.x); accA.y = fmaf(W00, v00.y, accA.y);
        accA.z = fmaf(W00, v00.z, accA.z); accA.w = fmaf(W00, v00.w, accA.w);
        accB.x = fmaf(W10, v10.x, accB.x); accB.y = fmaf(W10, v10.y, accB.y);
        accB.z = fmaf(W10, v10.z, accB.z); accB.w = fmaf(W10, v10.w, accB.w);
        accA.x = fmaf(W01, v01.x, accA.x); accA.y = fmaf(W01, v01.y, accA.y);
        accA.z = fmaf(W01, v01.z, accA.z); accA.w = fmaf(W01, v01.w, accA.w);
        accB.x = fmaf(W11, v11.x, accB.x); accB.y = fmaf(W11, v11.y, accB.y);
        accB.z = fmaf(W11, v11.z, accB.z); accB.w = fmaf(W11, v11.w, accB.w);
    }

    float4 acc;
    acc.x = accA.x + accB.x;
    acc.y = accA.y + accB.y;
    acc.z = accA.z + accB.z;
    acc.w = accA.w + accB.w;

    // out float4 index: bq*64 + hg*32 + lane (contiguous per warp)
    reinterpret_cast<float4*>(out)[(size_t)bq * (NH * HD / 4) + (hg << 5) + lane] = acc;
}

extern "C" void kernel_launch(void* const* d_in, const int* in_sizes, int n_in,
                              void* d_out, int out_size)
{
    const float* value = (const float*)d_in[0];
    // d_in[1] = value_spatial_shapes (int64), unused
    const float* loc = (const float*)d_in[2];
    const float* aw = (const float*)d_in[3];
    float* out = (float*)d_out;

    const int total_warps = BS * NQ * (NH / 4);      // 80000
    const int threads = 256;
    const int blocks = total_warps * 32 / threads;   // 10000 (exact)

    deform_attn_kernel_v6<<<blocks, threads>>>(value, loc, aw, out);
}

// round 13
// speedup vs baseline: 1.5963x; 1.0322x over previous
#include <cuda_runtime.h>
#include <cstdint>

// Problem constants (fixed-shape variant)
#define BS 4
#define NQ 10000
#define NH 8
#define HD 32
#define NP 4
#define SH 100
#define SW 100

// value layout: [b][pix][h][d], pix = y*SW + x  (pixel stride = 256 floats = 64 float4)
// loc: [b][q][h][0][p][2]   aw: [b][q][h][0][p]   out: [b][q][h*HD+d]
//
// One warp = (b, q, head-group hg) covering heads hg*4..hg*4+3.
// Consume mapping: g = lane>>3 (head in group), sub = lane&7 (float4 slot).
// Scalar bilinear math for the 16 (head,point) combos computed once by
// lanes 0..15 and broadcast via shfl.
// __launch_bounds__(256, 6) forces regs<=40 -> 6 CTAs/SM (48 warps).

__global__ __launch_bounds__(256, 6) void deform_attn_kernel_v6(
    const float* __restrict__ value,
    const float* __restrict__ loc,
    const float* __restrict__ aw,
    float* __restrict__ out)
{
    const int gtid = blockIdx.x * blockDim.x + threadIdx.x;
    const int warp = gtid >> 5;
    const int lane = gtid & 31;

    const int hg = warp & 1;
    const int bq = warp >> 1;           // b*NQ + q
    const int b  = bq / NQ;

    // ---- compute phase: lane c = lane&15 computes one (head, point) combo
    const int c   = lane & 15;          // head gc = c>>2, point pc = c&3
    const int idx = bq * (NH * NP) + (hg << 4) + c;

    const float2 l = __ldg(reinterpret_cast<const float2*>(loc) + idx);
    const float  w = __ldg(aw + idx);

    const float x = fmaf(l.x, (float)SW, -0.5f);
    const float y = fmaf(l.y, (float)SH, -0.5f);
    const int x0 = __float2int_rd(x);
    const int y0 = __float2int_rd(y);
    const float tx = x - (float)x0;
    const float ty = y - (float)y0;

    // factored weights: 6 mul/fma
    float wy1 = ty * w;
    float wy0 = w - wy1;
    float w00 = fmaf(-tx, wy0, wy0);
    float w10 = tx * wy0;
    float w01 = fmaf(-tx, wy1, wy1);
    float w11 = tx * wy1;

    const bool vx0 = (unsigned)x0       < (unsigned)SW;
    const bool vx1 = (unsigned)(x0 + 1) < (unsigned)SW;
    const bool vy0 = (unsigned)y0       < (unsigned)SH;
    const bool vy1 = (unsigned)(y0 + 1) < (unsigned)SH;

    if (!vx0) { w00 = 0.f; w01 = 0.f; }
    if (!vx1) { w10 = 0.f; w11 = 0.f; }
    if (!vy0) { w00 = 0.f; w10 = 0.f; }
    if (!vy1) { w01 = 0.f; w11 = 0.f; }

    const int xs0 = vx0 ? x0 : 0;
    const int xs1 = vx1 ? (x0 + 1) : 0;
    const int ys0 = vy0 ? y0 : 0;
    const int ys1 = vy1 ? (y0 + 1) : 0;

    // float4-unit offsets: pix*64 + head*8 (head = hg*4 + gc)
    const int hterm = ((hg << 2) + (c >> 2)) << 3;
    const int ra  = ys0 * (SW * 64) + hterm;
    const int dRb = (ys1 - ys0) * (SW * 64);     // rb = ra + dRb
    const int o00 = ra + (xs0 << 6);
    const int o10 = ra + (xs1 << 6);

    // ---- consume phase
    const int sub = lane & 7;
    const float4* __restrict__ vb =
        reinterpret_cast<const float4*>(value) +
        (size_t)b * (SH * SW * (NH * HD / 4)) + sub;

    const int srcbase = (lane >> 3) << 2;   // combos for my head: srcbase + p

    float4 accA = make_float4(0.f, 0.f, 0.f, 0.f);
    float4 accB = make_float4(0.f, 0.f, 0.f, 0.f);

#pragma unroll
    for (int p = 0; p < NP; ++p) {
        const int s = srcbase + p;
        const float W00 = __shfl_sync(0xffffffffu, w00, s);
        const float W10 = __shfl_sync(0xffffffffu, w10, s);
        const float W01 = __shfl_sync(0xffffffffu, w01, s);
        const float W11 = __shfl_sync(0xffffffffu, w11, s);
        const int   O00 = __shfl_sync(0xffffffffu, o00, s);
        const int   O10 = __shfl_sync(0xffffffffu, o10, s);
        const int   DRB = __shfl_sync(0xffffffffu, dRb, s);

        const float4 v00 = __ldg(vb + O00);
        const float4 v10 = __ldg(vb + O10);
        const float4 v01 = __ldg(vb + O00 + DRB);
        const float4 v11 = __ldg(vb + O10 + DRB);

        accA.x = fmaf(W00, v00.x, accA.x); accA.y = fmaf(W00, v00.y, accA.y);
        accA.z = fmaf(W00, v00.z, accA.z); accA.w = fmaf(W00, v00.w, accA.w);
        accB.x = fmaf(W10, v10.x, accB.x); accB.y = fmaf(W10, v10.y, accB.y);
        accB.z = fmaf(W10, v10.z, accB.z); accB.w = fmaf(W10, v10.w, accB.w);
        accA.x = fmaf(W01, v01.x, accA.x); accA.y = fmaf(W01, v01.y, accA.y);
        accA.z = fmaf(W01, v01.z, accA.z); accA.w = fmaf(W01, v01.w, accA.w);
        accB.x = fmaf(W11, v11.x, accB.x); accB.y = fmaf(W11, v11.y, accB.y);
        accB.z = fmaf(W11, v11.z, accB.z); accB.w = fmaf(W11, v11.w, accB.w);
    }

    float4 acc;
    acc.x = accA.x + accB.x;
    acc.y = accA.y + accB.y;
    acc.z = accA.z + accB.z;
    acc.w = accA.w + accB.w;

    // out float4 index: bq*64 + hg*32 + lane (contiguous per warp)
    reinterpret_cast<float4*>(out)[(size_t)bq * (NH * HD / 4) + (hg << 5) + lane] = acc;
}

extern "C" void kernel_launch(void* const* d_in, const int* in_sizes, int n_in,
                              void* d_out, int out_size)
{
    const float* value = (const float*)d_in[0];
    // d_in[1] = value_spatial_shapes (int64), unused
    const float* loc = (const float*)d_in[2];
    const float* aw = (const float*)d_in[3];
    float* out = (float*)d_out;

    const int total_warps = BS * NQ * (NH / 4);      // 80000
    const int threads = 256;
    const int blocks = total_warps * 32 / threads;   // 10000 (exact)

    deform_attn_kernel_v6<<<blocks, threads>>>(value, loc, aw, out);
}

// round 14
// speedup vs baseline: 1.6074x; 1.0070x over previous
#include <cuda_runtime.h>
#include <cstdint>

// Problem constants (fixed-shape variant)
#define BS 4
#define NQ 10000
#define NH 8
#define HD 32
#define NP 4
#define SH 100
#define SW 100

// value layout: [b][pix][h][d], pix = y*SW + x  (pixel stride = 256 floats = 64 float4)
// loc: [b][q][h][0][p][2]   aw: [b][q][h][0][p]   out: [b][q][h*HD+d]
//
// One warp = (b, q, head-group hg) covering heads hg*4..hg*4+3.
// Compute phase: lanes 0..15 each build ONE (head,point) package
// (4 masked weights float4 + 4 float4-unit offsets int4) -> smem (2x STS.128).
// Consume phase: g = lane>>3 (head), sub = lane&7 (float4 slot). Per point:
// 2 broadcast LDS.128 + 4 LDG.128 (each 8-lane group hits one 128B line).
// smem distribution (vs shfl) keeps the MIO pipe quiet and lets ptxas hoist
// all package reads / batch gather issue across the 4 points.

__global__ __launch_bounds__(256, 6) void deform_attn_kernel_v7(
    const float* __restrict__ value,
    const float* __restrict__ loc,
    const float* __restrict__ aw,
    float* __restrict__ out)
{
    __shared__ float4 s_w[8][16];   // [warp-in-block][combo]
    __shared__ int4   s_o[8][16];

    const int tid  = threadIdx.x;
    const int wib  = tid >> 5;
    const int lane = tid & 31;
    const int warp = blockIdx.x * 8 + wib;

    const int hg = warp & 1;
    const int bq = warp >> 1;           // b*NQ + q
    const int b  = bq / NQ;

    // ---- compute phase: lane c = lane&15 builds one (head, point) combo
    {
        const int c   = lane & 15;      // head gc = c>>2, point pc = c&3
        const int idx = bq * (NH * NP) + (hg << 4) + c;

        const float2 l = __ldg(reinterpret_cast<const float2*>(loc) + idx);
        const float  w = __ldg(aw + idx);

        const float x = fmaf(l.x, (float)SW, -0.5f);
        const float y = fmaf(l.y, (float)SH, -0.5f);
        const int x0 = __float2int_rd(x);
        const int y0 = __float2int_rd(y);
        const float tx = x - (float)x0;
        const float ty = y - (float)y0;

        // factored weights: 6 mul/fma
        const float wy1 = ty * w;
        const float wy0 = w - wy1;
        float w00 = fmaf(-tx, wy0, wy0);
        float w10 = tx * wy0;
        float w01 = fmaf(-tx, wy1, wy1);
        float w11 = tx * wy1;

        const bool vx0 = (unsigned)x0       < (unsigned)SW;
        const bool vx1 = (unsigned)(x0 + 1) < (unsigned)SW;
        const bool vy0 = (unsigned)y0       < (unsigned)SH;
        const bool vy1 = (unsigned)(y0 + 1) < (unsigned)SH;

        if (!vx0) { w00 = 0.f; w01 = 0.f; }
        if (!vx1) { w10 = 0.f; w11 = 0.f; }
        if (!vy0) { w00 = 0.f; w10 = 0.f; }
        if (!vy1) { w01 = 0.f; w11 = 0.f; }

        const int xs0 = vx0 ? x0 : 0;
        const int xs1 = vx1 ? (x0 + 1) : 0;
        const int ys0 = vy0 ? y0 : 0;
        const int ys1 = vy1 ? (y0 + 1) : 0;

        // float4-unit offsets: pix*64 + head*8 (head = hg*4 + gc)
        const int hterm = ((hg << 2) + (c >> 2)) << 3;
        const int ra = ys0 * (SW * 64) + hterm;
        const int rb = ys1 * (SW * 64) + hterm;
        const int ca = xs0 << 6;
        const int cb = xs1 << 6;

        if (lane < 16) {
            s_w[wib][c] = make_float4(w00, w10, w01, w11);
            s_o[wib][c] = make_int4(ra + ca, ra + cb, rb + ca, rb + cb);
        }
    }
    __syncwarp();

    // ---- consume phase
    const int sub = lane & 7;
    const float4* __restrict__ vb =
        reinterpret_cast<const float4*>(value) +
        (size_t)b * (SH * SW * (NH * HD / 4)) + sub;

    const int srcbase = (lane >> 3) << 2;   // combos for my head: srcbase + p

    float4 accA = make_float4(0.f, 0.f, 0.f, 0.f);
    float4 accB = make_float4(0.f, 0.f, 0.f, 0.f);

#pragma unroll
    for (int p = 0; p < NP; ++p) {
        const float4 W = s_w[wib][srcbase + p];
        const int4   O = s_o[wib][srcbase + p];

        const float4 v00 = __ldg(vb + O.x);
        const float4 v10 = __ldg(vb + O.y);
        const float4 v01 = __ldg(vb + O.z);
        const float4 v11 = __ldg(vb + O.w);

        accA.x = fmaf(W.x, v00.x, accA.x); accA.y = fmaf(W.x, v00.y, accA.y);
        accA.z = fmaf(W.x, v00.z, accA.z); accA.w = fmaf(W.x, v00.w, accA.w);
        accB.x = fmaf(W.y, v10.x, accB.x); accB.y = fmaf(W.y, v10.y, accB.y);
        accB.z = fmaf(W.y, v10.z, accB.z); accB.w = fmaf(W.y, v10.w, accB.w);
        accA.x = fmaf(W.z, v01.x, accA.x); accA.y = fmaf(W.z, v01.y, accA.y);
        accA.z = fmaf(W.z, v01.z, accA.z); accA.w = fmaf(W.z, v01.w, accA.w);
        accB.x = fmaf(W.w, v11.x, accB.x); accB.y = fmaf(W.w, v11.y, accB.y);
        accB.z = fmaf(W.w, v11.z, accB.z); accB.w = fmaf(W.w, v11.w, accB.w);
    }

    float4 acc;
    acc.x = accA.x + accB.x;
    acc.y = accA.y + accB.y;
    acc.z = accA.z + accB.z;
    acc.w = accA.w + accB.w;

    // out float4 index: bq*64 + hg*32 + lane (contiguous per warp)
    reinterpret_cast<float4*>(out)[(size_t)bq * (NH * HD / 4) + (hg << 5) + lane] = acc;
}

extern "C" void kernel_launch(void* const* d_in, const int* in_sizes, int n_in,
                              void* d_out, int out_size)
{
    const float* value = (const float*)d_in[0];
    // d_in[1] = value_spatial_shapes (int64), unused
    const float* loc = (const float*)d_in[2];
    const float* aw = (const float*)d_in[3];
    float* out = (float*)d_out;

    const int total_warps = BS * NQ * (NH / 4);      // 80000
    const int threads = 256;
    const int blocks = total_warps * 32 / threads;   // 10000 (exact)

    deform_attn_kernel_v7<<<blocks, threads>>>(value, loc, aw, out);
}